// round 8
// baseline (speedup 1.0000x reference)
#include <cuda_runtime.h>

// ConvSBS fused contraction, P=8 pixel batching, f32x2 SIMD, cores via L1-cached LDG.
// channels: [2, 8, 128, 128, 4] f32 ; cores: [4, 2, 8, 8, 4, 4] f32 ; out: [8,127,127,16] f32

typedef unsigned long long ull;

__device__ __forceinline__ ull pk2(float lo, float hi) {
    ull d; asm("mov.b64 %0, {%1, %2};" : "=l"(d) : "f"(lo), "f"(hi)); return d;
}
__device__ __forceinline__ float2 up2(ull v) {
    float2 r; asm("mov.b64 {%0, %1}, %2;" : "=f"(r.x), "=f"(r.y) : "l"(v)); return r;
}
__device__ __forceinline__ ull fma2(ull a, ull b, ull c) {
    ull d; asm("fma.rn.f32x2 %0, %1, %2, %3;" : "=l"(d) : "l"(a), "l"(b), "l"(c)); return d;
}
__device__ __forceinline__ ull mul2(ull a, ull b) {
    ull d; asm("mul.rn.f32x2 %0, %1, %2;" : "=l"(d) : "l"(a), "l"(b)); return d;
}
__device__ __forceinline__ ull add2(ull a, ull b) {
    ull d; asm("add.rn.f32x2 %0, %1, %2;" : "=l"(d) : "l"(a), "l"(b)); return d;
}

#define BATCH 8
#define H 128
#define W 128
#define OH 127
#define OW 127
#define GX 16                               // groups of 8 px per row
#define TOT_GROUPS (BATCH * OH * GX)        // 16256

#define WARPS_PER_CTA 5
#define NTHREADS (WARPS_PER_CTA * 32)
#define NCTAS 296

// Relayout core table: g_core[(bi*16 + ac)*64 + lr], bi = t*2+q, ac = a*4+c.
__device__ float g_core[8192];

// Per-pair scratch buffer: 640 ull.
//   M element (bi, row, col) at ull idx bi*80 + row*10 + col.
//   Overlay: Bsm[rs][k][i] at rs*82 + k*10 + i ; Psm at 336 + (q*8+i)*10 + q*8 + o8.
#define PAIR_ULL 640
#define WARP_ULL (4 * PAIR_ULL)
#define SMEM_F  (WARPS_PER_CTA * WARP_ULL * 2)

__global__ void relayout_kernel(const float* __restrict__ cores) {
    int idx = blockIdx.x * blockDim.x + threadIdx.x;
    if (idx < 8192) {
        int c = idx & 3, a = (idx >> 2) & 3, r = (idx >> 4) & 7;
        int l = (idx >> 7) & 7, q = (idx >> 10) & 1, t = idx >> 11;
        g_core[(((t * 2 + q) * 16 + (a * 4 + c)) << 6) + (l * 8 + r)] = cores[idx];
    }
}

__global__ void __launch_bounds__(NTHREADS, 2) convsbs_kernel(
    const float* __restrict__ channels,
    float* __restrict__ out)
{
    extern __shared__ float smem[];
    const int tid = threadIdx.x;
    const int warp = tid >> 5;
    const int lane = tid & 31;
    ull* Wb = (ull*)smem + warp * WARP_ULL;

    const int g2 = lane >> 4;        // q (A-stage) / s (B-stage) / q (final)
    const int i2 = (lane >> 1) & 7;  // i (A) / k (B) / i (final)
    const int h2 = lane & 1;         // k-half (A) / i-half (B)

    const float* __restrict__ ch0 = channels;
    const float* __restrict__ ch1 = channels + BATCH * H * W * 4;
    const float2* __restrict__ gc = (const float2*)g_core;  // per-lane float2 at (bi*16+ac)*32 + lane
    const ull z = pk2(0.f, 0.f);
    const int nwork = gridDim.x * WARPS_PER_CTA;

    for (int g = blockIdx.x * WARPS_PER_CTA + warp; g < TOT_GROUPS; g += nwork) {
        int b   = g / (OH * GX);
        int rem = g - b * (OH * GX);
        int y   = rem >> 4;
        int x0  = (rem & 15) << 3;          // group covers out-x x0..x0+7 (4 pairs)

        // ========== Stage 1: M for pairs p = (x0+2p, x0+2p+1), p=0..3 ==========
        #pragma unroll
        for (int t = 0; t < 4; t++) {
            const int py  = y + (t >> 1);
            const int cxb = x0 + (t & 1);
            float4 c0v[8], c1v[8];
            #pragma unroll
            for (int d = 0; d < 8; d++) {
                int cx = min(cxb + d, W - 1);
                int base = ((b * H + py) * W + cx) * 4;
                c0v[d] = *(const float4*)(ch0 + base);
                c1v[d] = *(const float4*)(ch1 + base);
            }
            ull c0p[4][4], c1p[4][4];
            #pragma unroll
            for (int p = 0; p < 4; p++) {
                c0p[p][0] = pk2(c0v[2*p].x, c0v[2*p+1].x);
                c0p[p][1] = pk2(c0v[2*p].y, c0v[2*p+1].y);
                c0p[p][2] = pk2(c0v[2*p].z, c0v[2*p+1].z);
                c0p[p][3] = pk2(c0v[2*p].w, c0v[2*p+1].w);
                c1p[p][0] = pk2(c1v[2*p].x, c1v[2*p+1].x);
                c1p[p][1] = pk2(c1v[2*p].y, c1v[2*p+1].y);
                c1p[p][2] = pk2(c1v[2*p].z, c1v[2*p+1].z);
                c1p[p][3] = pk2(c1v[2*p].w, c1v[2*p+1].w);
            }

            ull acc[2][4][2];   // [q][pair][entry 2L / 2L+1]
            #pragma unroll
            for (int q = 0; q < 2; q++)
                #pragma unroll
                for (int p = 0; p < 4; p++) { acc[q][p][0] = z; acc[q][p][1] = z; }

            #pragma unroll
            for (int a = 0; a < 4; a++) {
                #pragma unroll
                for (int c = 0; c < 4; c++) {
                    ull v[4];
                    #pragma unroll
                    for (int p = 0; p < 4; p++) v[p] = mul2(c0p[p][a], c1p[p][c]);
                    const int ac = a * 4 + c;
                    #pragma unroll
                    for (int q = 0; q < 2; q++) {
                        float2 f = __ldg(&gc[((t * 2 + q) * 16 + ac) * 32 + lane]);
                        ull cx2 = pk2(f.x, f.x);
                        ull cy2 = pk2(f.y, f.y);
                        #pragma unroll
                        for (int p = 0; p < 4; p++) {
                            acc[q][p][0] = fma2(cx2, v[p], acc[q][p][0]);
                            acc[q][p][1] = fma2(cy2, v[p], acc[q][p][1]);
                        }
                    }
                }
            }

            const int row = lane >> 2;        // l of entry lr = 2*lane
            const int col = 2 * (lane & 3);   // r of entry lr = 2*lane
            const int midx = row * 10 + col;
            #pragma unroll
            for (int q = 0; q < 2; q++) {
                const int bi = t * 2 + q;
                #pragma unroll
                for (int p = 0; p < 4; p++)
                    *(ulonglong2*)(Wb + p * PAIR_ULL + bi * 80 + midx) =
                        make_ulonglong2(acc[q][p][0], acc[q][p][1]);
            }
        }
        __syncwarp();

        // ========== Stage 2 per pair ==========
        #pragma unroll
        for (int pr = 0; pr < 4; pr++) {
            ull* M = Wb + pr * PAIR_ULL;

            // ---- A-stage: lane (q=g2, i=i2, kh=h2), both p accumulated ----
            ull a2[2][4];
            {
                ull rm0[2][8];
                #pragma unroll
                for (int p = 0; p < 2; p++) {
                    #pragma unroll
                    for (int c = 0; c < 4; c++) {
                        ulonglong2 u = *(const ulonglong2*)(M + p * 80 + i2 * 10 + 2 * c);
                        rm0[p][2 * c] = u.x; rm0[p][2 * c + 1] = u.y;
                    }
                }
                #pragma unroll
                for (int p = 0; p < 2; p++)
                    #pragma unroll
                    for (int kk = 0; kk < 4; kk++) a2[p][kk] = z;
                #pragma unroll
                for (int j = 0; j < 8; j++) {
                    ulonglong2 m1a = *(const ulonglong2*)(M + (2 + g2) * 80 + j * 10 + h2 * 4);
                    ulonglong2 m1b = *(const ulonglong2*)(M + (2 + g2) * 80 + j * 10 + h2 * 4 + 2);
                    #pragma unroll
                    for (int p = 0; p < 2; p++) {
                        a2[p][0] = fma2(rm0[p][j], m1a.x, a2[p][0]);
                        a2[p][1] = fma2(rm0[p][j], m1a.y, a2[p][1]);
                        a2[p][2] = fma2(rm0[p][j], m1b.x, a2[p][2]);
                        a2[p][3] = fma2(rm0[p][j], m1b.y, a2[p][3]);
                    }
                }
            }

            // ---- B-stage: lane (s=g2, k=i2, ih=h2), both r accumulated ----
            ull bt[2][4];
            {
                ull rm2[2][8];
                #pragma unroll
                for (int r = 0; r < 2; r++) {
                    #pragma unroll
                    for (int c = 0; c < 4; c++) {
                        ulonglong2 u = *(const ulonglong2*)(M + (4 + r) * 80 + i2 * 10 + 2 * c);
                        rm2[r][2 * c] = u.x; rm2[r][2 * c + 1] = u.y;
                    }
                }
                #pragma unroll
                for (int r = 0; r < 2; r++)
                    #pragma unroll
                    for (int ii = 0; ii < 4; ii++) bt[r][ii] = z;
                #pragma unroll
                for (int l = 0; l < 8; l++) {
                    ulonglong2 m3a = *(const ulonglong2*)(M + (6 + g2) * 80 + l * 10 + h2 * 4);
                    ulonglong2 m3b = *(const ulonglong2*)(M + (6 + g2) * 80 + l * 10 + h2 * 4 + 2);
                    #pragma unroll
                    for (int r = 0; r < 2; r++) {
                        bt[r][0] = fma2(rm2[r][l], m3a.x, bt[r][0]);
                        bt[r][1] = fma2(rm2[r][l], m3a.y, bt[r][1]);
                        bt[r][2] = fma2(rm2[r][l], m3b.x, bt[r][2]);
                        bt[r][3] = fma2(rm2[r][l], m3b.y, bt[r][3]);
                    }
                }
            }
            __syncwarp();

            // ---- store B: Bsm[rs][k][i] at rs*82 + k*10 + i  (rs = r*2 + s) ----
            #pragma unroll
            for (int r = 0; r < 2; r++) {
                const int base = (r * 2 + g2) * 82 + i2 * 10 + h2 * 4;
                *(ulonglong2*)(M + base)     = make_ulonglong2(bt[r][0], bt[r][1]);
                *(ulonglong2*)(M + base + 2) = make_ulonglong2(bt[r][2], bt[r][3]);
            }
            __syncwarp();

            // ---- final partials at lane (q=g2, i=i2, kh=h2) ----
            ull part[2][4];
            #pragma unroll
            for (int p = 0; p < 2; p++)
                #pragma unroll
                for (int rs = 0; rs < 4; rs++) part[p][rs] = z;
            #pragma unroll
            for (int rs = 0; rs < 4; rs++) {
                #pragma unroll
                for (int kk = 0; kk < 4; kk++) {
                    ull Bv = M[rs * 82 + (h2 * 4 + kk) * 10 + i2];
                    part[0][rs] = fma2(a2[0][kk], Bv, part[0][rs]);
                    part[1][rs] = fma2(a2[1][kk], Bv, part[1][rs]);
                }
            }
            #pragma unroll
            for (int p = 0; p < 2; p++)
                #pragma unroll
                for (int rs = 0; rs < 4; rs++)
                    part[p][rs] = add2(part[p][rs],
                                       __shfl_xor_sync(0xffffffffu, part[p][rs], 1));
            if (h2 == 0) {
                const int pbase = 336 + (g2 * 8 + i2) * 10 + g2 * 8;
                *(ulonglong2*)(M + pbase)     = make_ulonglong2(part[0][0], part[0][1]);
                *(ulonglong2*)(M + pbase + 2) = make_ulonglong2(part[0][2], part[0][3]);
                *(ulonglong2*)(M + pbase + 4) = make_ulonglong2(part[1][0], part[1][1]);
                *(ulonglong2*)(M + pbase + 6) = make_ulonglong2(part[1][2], part[1][3]);
            }
            __syncwarp();

            // ---- output: lanes 0..15, q=lane>>3, o8=lane&7 (p=o8>>2, rs=o8&3) ----
            if (lane < 16) {
                const int q = lane >> 3, o8 = lane & 7;
                ull s = z;
                #pragma unroll
                for (int i = 0; i < 8; i++)
                    s = add2(s, M[336 + (q * 8 + i) * 10 + q * 8 + o8]);
                const int p = o8 >> 2, rs = o8 & 3;
                const int outIdx = p * 8 + q * 4 + rs;
                const int xx = x0 + pr * 2;
                const int pix0 = (b * OH + y) * OW + xx;
                float2 pv = up2(s);
                out[pix0 * 16 + outIdx] = pv.x;
                if (xx + 1 < OW)
                    out[(pix0 + 1) * 16 + outIdx] = pv.y;
            }
            __syncwarp();
        }
    }
}

extern "C" void kernel_launch(void* const* d_in, const int* in_sizes, int n_in,
                              void* d_out, int out_size)
{
    const float* channels = (const float*)d_in[0];
    const float* cores    = (const float*)d_in[1];
    float* out            = (float*)d_out;

    static bool attr_set = false;
    if (!attr_set) {
        cudaFuncSetAttribute(convsbs_kernel,
                             cudaFuncAttributeMaxDynamicSharedMemorySize,
                             SMEM_F * sizeof(float));
        attr_set = true;
    }
    relayout_kernel<<<8, 1024>>>(cores);
    convsbs_kernel<<<NCTAS, NTHREADS, SMEM_F * sizeof(float)>>>(channels, out);
}

// round 9
// speedup vs baseline: 1.4008x; 1.4008x over previous
#include <cuda_runtime.h>

// ConvSBS fused contraction, pixel-pair SIMD (f32x2).
// channels: [2, 8, 128, 128, 4] f32 ; cores: [4, 2, 8, 8, 4, 4] f32 ; out: [8,127,127,16] f32

typedef unsigned long long ull;

__device__ __forceinline__ ull pk2(float lo, float hi) {
    ull d; asm("mov.b64 %0, {%1, %2};" : "=l"(d) : "f"(lo), "f"(hi)); return d;
}
__device__ __forceinline__ float2 up2(ull v) {
    float2 r; asm("mov.b64 {%0, %1}, %2;" : "=f"(r.x), "=f"(r.y) : "l"(v)); return r;
}
__device__ __forceinline__ ull fma2(ull a, ull b, ull c) {
    ull d; asm("fma.rn.f32x2 %0, %1, %2, %3;" : "=l"(d) : "l"(a), "l"(b), "l"(c)); return d;
}
__device__ __forceinline__ ull mul2(ull a, ull b) {
    ull d; asm("mul.rn.f32x2 %0, %1, %2;" : "=l"(d) : "l"(a), "l"(b)); return d;
}
__device__ __forceinline__ ull add2(ull a, ull b) {
    ull d; asm("add.rn.f32x2 %0, %1, %2;" : "=l"(d) : "l"(a), "l"(b)); return d;
}

#define BATCH 8
#define H 128
#define W 128
#define OH 127
#define OW 127
#define GX 32
#define TOT_GROUPS (BATCH * OH * GX)

#define WARPS_PER_CTA 8
#define NTHREADS (WARPS_PER_CTA * 32)
#define NCTAS 296

// Cores in smem, swizzled layout (4 KB per block bi):
//   lane L owns lr entries (2L, 2L+1); chunk c at ull idx bi*512 + L*16 + ((c+L)&7)*2.
//
// Per-pair scratch: 640 ull.
//   M block stride 78 (bank-skewed): element (bi,row,col) at bi*78 + row*10 + col.
//     (max used idx in block = 77; g2-block bank offset = 2*78 mod 32 = 28 -> the four
//      (g2,h2) broadcast groups in stage-2 j/l loops hit disjoint bank spans.)
//   Overlay: Bsm[rs][k][i] at rs*82 + k*10 + i (max 325, written after blocks 0..7 read);
//            Psm at 336 + (q*8+i)*10 + q*8 + o8 (max 501).
#define MBS 78
#define PAIR_ULL 640
#define WARP_ULL (2 * PAIR_ULL)
#define CORES_F 8192
#define SMEM_F  (CORES_F + WARPS_PER_CTA * WARP_ULL * 2)

__global__ void __launch_bounds__(NTHREADS, 2) convsbs_kernel(
    const float* __restrict__ channels,
    const float* __restrict__ cores,
    float* __restrict__ out)
{
    extern __shared__ float smem[];
    const int tid = threadIdx.x;
    ull* coreU = (ull*)smem;

    // cores relayout: [t][q][l][r][a][c4] -> swizzled per-lane chunks
    for (int idx = tid; idx < 8192; idx += NTHREADS) {
        int c4 = idx & 3, a = (idx >> 2) & 3, r = (idx >> 4) & 7;
        int l = (idx >> 7) & 7, q = (idx >> 10) & 1, t = idx >> 11;
        int bi = t * 2 + q;
        int lr = l * 8 + r;
        int L = lr >> 1, half = lr & 1;
        int ac = a * 4 + c4;
        int chunk = ac >> 1, pos = ac & 1;
        int uidx = bi * 512 + L * 16 + (((chunk + L) & 7) << 1) + pos;
        smem[uidx * 2 + half] = cores[idx];
    }
    __syncthreads();

    const int warp = tid >> 5;
    const int lane = tid & 31;
    ull* Wb = (ull*)(smem + CORES_F) + warp * WARP_ULL;

    const int g2 = lane >> 4;        // q (A-stage) / s (B-stage) / q (final)
    const int i2 = (lane >> 1) & 7;  // i (A) / k (B) / i (final)
    const int h2 = lane & 1;         // k-half (A) / i-half (B)

    const float* __restrict__ ch0 = channels;
    const float* __restrict__ ch1 = channels + BATCH * H * W * 4;
    const ull z = pk2(0.f, 0.f);
    const int nwork = gridDim.x * WARPS_PER_CTA;

    for (int g = blockIdx.x * WARPS_PER_CTA + warp; g < TOT_GROUPS; g += nwork) {
        int b   = g / (OH * GX);
        int rem = g - b * (OH * GX);
        int y   = rem >> 5;
        int x0  = (rem & 31) << 2;

        // ========== Stage 1: M for pairs A=(x0,x0+1), B=(x0+2,x0+3) ==========
        #pragma unroll
        for (int t = 0; t < 4; t++) {
            const int py  = y + (t >> 1);
            const int cxb = x0 + (t & 1);
            float4 c0[4], c1[4];
            #pragma unroll
            for (int d = 0; d < 4; d++) {
                int cx = min(cxb + d, W - 1);
                int base = ((b * H + py) * W + cx) * 4;
                c0[d] = *(const float4*)(ch0 + base);
                c1[d] = *(const float4*)(ch1 + base);
            }
            ull c0A[4], c1A[4], c0B[4], c1B[4];
            c0A[0]=pk2(c0[0].x,c0[1].x); c0A[1]=pk2(c0[0].y,c0[1].y);
            c0A[2]=pk2(c0[0].z,c0[1].z); c0A[3]=pk2(c0[0].w,c0[1].w);
            c1A[0]=pk2(c1[0].x,c1[1].x); c1A[1]=pk2(c1[0].y,c1[1].y);
            c1A[2]=pk2(c1[0].z,c1[1].z); c1A[3]=pk2(c1[0].w,c1[1].w);
            c0B[0]=pk2(c0[2].x,c0[3].x); c0B[1]=pk2(c0[2].y,c0[3].y);
            c0B[2]=pk2(c0[2].z,c0[3].z); c0B[3]=pk2(c0[2].w,c0[3].w);
            c1B[0]=pk2(c1[2].x,c1[3].x); c1B[1]=pk2(c1[2].y,c1[3].y);
            c1B[2]=pk2(c1[2].z,c1[3].z); c1B[3]=pk2(c1[2].w,c1[3].w);

            ull vA[16], vB[16];
            #pragma unroll
            for (int a = 0; a < 4; a++)
                #pragma unroll
                for (int c = 0; c < 4; c++) {
                    vA[a * 4 + c] = mul2(c0A[a], c1A[c]);
                    vB[a * 4 + c] = mul2(c0B[a], c1B[c]);
                }

            const int row = lane >> 2;        // l of entry lr = 2*lane
            const int col = 2 * (lane & 3);   // r of entry lr = 2*lane
            #pragma unroll
            for (int q = 0; q < 2; q++) {
                const int bi = t * 2 + q;
                const float4* cp4 = (const float4*)(coreU + bi * 512 + lane * 16);
                ull aA0 = z, aA1 = z, aB0 = z, aB1 = z;
                #pragma unroll
                for (int c = 0; c < 8; c++) {
                    float4 f = cp4[(c + lane) & 7];   // ac=2c: (f.x,f.y); ac=2c+1: (f.z,f.w)
                    ull cx2 = pk2(f.x, f.x);
                    ull cy2 = pk2(f.y, f.y);
                    aA0 = fma2(cx2, vA[2 * c], aA0);
                    aA1 = fma2(cy2, vA[2 * c], aA1);
                    aB0 = fma2(cx2, vB[2 * c], aB0);
                    aB1 = fma2(cy2, vB[2 * c], aB1);
                    ull cz2 = pk2(f.z, f.z);
                    ull cw2 = pk2(f.w, f.w);
                    aA0 = fma2(cz2, vA[2 * c + 1], aA0);
                    aA1 = fma2(cw2, vA[2 * c + 1], aA1);
                    aB0 = fma2(cz2, vB[2 * c + 1], aB0);
                    aB1 = fma2(cw2, vB[2 * c + 1], aB1);
                }
                const int midx = bi * MBS + row * 10 + col;
                *(ulonglong2*)(Wb + midx)            = make_ulonglong2(aA0, aA1);
                *(ulonglong2*)(Wb + PAIR_ULL + midx) = make_ulonglong2(aB0, aB1);
            }
        }
        __syncwarp();

        // ========== Stage 2 per pair ==========
        #pragma unroll
        for (int pr = 0; pr < 2; pr++) {
            ull* M = Wb + pr * PAIR_ULL;

            // ---- A-stage: lane (q=g2, i=i2, kh=h2), both p accumulated ----
            ull a2[2][4];
            {
                ull rm0[2][8];
                #pragma unroll
                for (int p = 0; p < 2; p++) {
                    #pragma unroll
                    for (int c = 0; c < 4; c++) {
                        ulonglong2 u = *(const ulonglong2*)(M + p * MBS + i2 * 10 + 2 * c);
                        rm0[p][2 * c] = u.x; rm0[p][2 * c + 1] = u.y;
                    }
                }
                #pragma unroll
                for (int p = 0; p < 2; p++)
                    #pragma unroll
                    for (int kk = 0; kk < 4; kk++) a2[p][kk] = z;
                #pragma unroll
                for (int j = 0; j < 8; j++) {
                    ulonglong2 m1a = *(const ulonglong2*)(M + (2 + g2) * MBS + j * 10 + h2 * 4);
                    ulonglong2 m1b = *(const ulonglong2*)(M + (2 + g2) * MBS + j * 10 + h2 * 4 + 2);
                    #pragma unroll
                    for (int p = 0; p < 2; p++) {
                        a2[p][0] = fma2(rm0[p][j], m1a.x, a2[p][0]);
                        a2[p][1] = fma2(rm0[p][j], m1a.y, a2[p][1]);
                        a2[p][2] = fma2(rm0[p][j], m1b.x, a2[p][2]);
                        a2[p][3] = fma2(rm0[p][j], m1b.y, a2[p][3]);
                    }
                }
            }

            // ---- B-stage: lane (s=g2, k=i2, ih=h2), both r accumulated ----
            ull bt[2][4];
            {
                ull rm2[2][8];
                #pragma unroll
                for (int r = 0; r < 2; r++) {
                    #pragma unroll
                    for (int c = 0; c < 4; c++) {
                        ulonglong2 u = *(const ulonglong2*)(M + (4 + r) * MBS + i2 * 10 + 2 * c);
                        rm2[r][2 * c] = u.x; rm2[r][2 * c + 1] = u.y;
                    }
                }
                #pragma unroll
                for (int r = 0; r < 2; r++)
                    #pragma unroll
                    for (int ii = 0; ii < 4; ii++) bt[r][ii] = z;
                #pragma unroll
                for (int l = 0; l < 8; l++) {
                    ulonglong2 m3a = *(const ulonglong2*)(M + (6 + g2) * MBS + l * 10 + h2 * 4);
                    ulonglong2 m3b = *(const ulonglong2*)(M + (6 + g2) * MBS + l * 10 + h2 * 4 + 2);
                    #pragma unroll
                    for (int r = 0; r < 2; r++) {
                        bt[r][0] = fma2(rm2[r][l], m3a.x, bt[r][0]);
                        bt[r][1] = fma2(rm2[r][l], m3a.y, bt[r][1]);
                        bt[r][2] = fma2(rm2[r][l], m3b.x, bt[r][2]);
                        bt[r][3] = fma2(rm2[r][l], m3b.y, bt[r][3]);
                    }
                }
            }
            __syncwarp();

            // ---- store B: Bsm[rs][k][i] at rs*82 + k*10 + i  (rs = r*2 + s) ----
            #pragma unroll
            for (int r = 0; r < 2; r++) {
                const int base = (r * 2 + g2) * 82 + i2 * 10 + h2 * 4;
                *(ulonglong2*)(M + base)     = make_ulonglong2(bt[r][0], bt[r][1]);
                *(ulonglong2*)(M + base + 2) = make_ulonglong2(bt[r][2], bt[r][3]);
            }
            __syncwarp();

            // ---- final partials at lane (q=g2, i=i2, kh=h2) ----
            ull part[2][4];
            #pragma unroll
            for (int p = 0; p < 2; p++)
                #pragma unroll
                for (int rs = 0; rs < 4; rs++) part[p][rs] = z;
            #pragma unroll
            for (int rs = 0; rs < 4; rs++) {
                #pragma unroll
                for (int kk = 0; kk < 4; kk++) {
                    ull Bv = M[rs * 82 + (h2 * 4 + kk) * 10 + i2];
                    part[0][rs] = fma2(a2[0][kk], Bv, part[0][rs]);
                    part[1][rs] = fma2(a2[1][kk], Bv, part[1][rs]);
                }
            }
            #pragma unroll
            for (int p = 0; p < 2; p++)
                #pragma unroll
                for (int rs = 0; rs < 4; rs++)
                    part[p][rs] = add2(part[p][rs],
                                       __shfl_xor_sync(0xffffffffu, part[p][rs], 1));
            if (h2 == 0) {
                const int pbase = 336 + (g2 * 8 + i2) * 10 + g2 * 8;
                *(ulonglong2*)(M + pbase)     = make_ulonglong2(part[0][0], part[0][1]);
                *(ulonglong2*)(M + pbase + 2) = make_ulonglong2(part[0][2], part[0][3]);
                *(ulonglong2*)(M + pbase + 4) = make_ulonglong2(part[1][0], part[1][1]);
                *(ulonglong2*)(M + pbase + 6) = make_ulonglong2(part[1][2], part[1][3]);
            }
            __syncwarp();

            // ---- output: lanes 0..15, q=lane>>3, o8=lane&7 (p=o8>>2, rs=o8&3) ----
            if (lane < 16) {
                const int q = lane >> 3, o8 = lane & 7;
                ull s = z;
                #pragma unroll
                for (int i = 0; i < 8; i++)
                    s = add2(s, M[336 + (q * 8 + i) * 10 + q * 8 + o8]);
                const int p = o8 >> 2, rs = o8 & 3;
                const int outIdx = p * 8 + q * 4 + rs;
                const int xx = x0 + pr * 2;
                const int pix0 = (b * OH + y) * OW + xx;
                float2 pv = up2(s);
                out[pix0 * 16 + outIdx] = pv.x;
                if (xx + 1 < OW)
                    out[(pix0 + 1) * 16 + outIdx] = pv.y;
            }
            __syncwarp();
        }
    }
}

extern "C" void kernel_launch(void* const* d_in, const int* in_sizes, int n_in,
                              void* d_out, int out_size)
{
    const float* channels = (const float*)d_in[0];
    const float* cores    = (const float*)d_in[1];
    float* out            = (float*)d_out;

    static bool attr_set = false;
    if (!attr_set) {
        cudaFuncSetAttribute(convsbs_kernel,
                             cudaFuncAttributeMaxDynamicSharedMemorySize,
                             SMEM_F * sizeof(float));
        attr_set = true;
    }
    convsbs_kernel<<<NCTAS, NTHREADS, SMEM_F * sizeof(float)>>>(channels, cores, out);
}